// round 12
// baseline (speedup 1.0000x reference)
#include <cuda_runtime.h>
#include <math.h>

#define NEARV     2.0f
#define FARV      6.0f
#define FAR_DIST  1e10f
#define S         128
#define TPB       128          // 4 warps, 8 rays per block
#define MAX_BLK   16384
#define FULL      0xffffffffu

// Deterministic scratch for the fused scalar reduction (no allocations allowed).
__device__ float        g_partials[MAX_BLK];
__device__ unsigned int g_count = 0;

__global__ __launch_bounds__(TPB, 8) void integrate_kernel(
    const float* __restrict__ raw,     // [N, S, 4]
    const float* __restrict__ zvals,   // [N, S]
    const float* __restrict__ rays_d,  // [N, 3]
    float* __restrict__ out,           // [3N chs | N depth | 1 scalar]
    int N)
{
    __shared__ float  sh_ent[TPB / 32];
    __shared__ double sh_red[TPB];
    __shared__ bool   sh_last;

    const int warp = threadIdx.x >> 5;
    const int lane = threadIdx.x & 31;
    const int half = lane >> 4;              // 0 -> ray A, 1 -> ray B
    const int l    = lane & 15;              // lane within 16-lane ray group
    int ray = (blockIdx.x * (TPB >> 5) + warp) * 2 + half;
    const bool active = (ray < N);
    if (!active) ray = N - 1;                // clamp: safe reads, stores guarded

    const float4* rp = (const float4*)raw + (size_t)ray * S;
    const float*  zp = zvals + (size_t)ray * S;
    const float*  sp = raw + (size_t)ray * (S * 4) + 3;   // sigma stream

    // ---- front-batched loads: sigma (scalar, same L1 lines as float4),
    //      z and z-next. Colors reloaded later as L1 hits. ----
    float sig[8], z[8], zx[8];
    #pragma unroll
    for (int k = 0; k < 8; k++) sig[k] = sp[(16 * k + l) * 4];
    #pragma unroll
    for (int k = 0; k < 8; k++) {
        const int j = 16 * k + l;
        z[k]  = zp[j];
        zx[k] = zp[(j + 1 < S) ? j + 1 : (S - 1)];   // contiguous; L1 hits
    }

    const float* rd = rays_d + (size_t)ray * 3;
    const float nrm = sqrtf(rd[0] * rd[0] + rd[1] * rd[1] + rd[2] * rd[2]);

    // ---- alpha / transmittance factors ----
    float a[8], t[8];
    #pragma unroll
    for (int k = 0; k < 8; k++) {
        const int j = 16 * k + l;
        const float dist = ((j == S - 1) ? FAR_DIST : (zx[k] - z[k])) * nrm;
        const float e = __expf(-fmaxf(sig[k], 0.0f) * dist);
        a[k] = 1.0f - e;
        t[k] = e + 1e-10f;
    }

    // ---- 8 segmented (width-16) inclusive multiplicative scans ----
    #pragma unroll
    for (int off = 1; off < 16; off <<= 1) {
        #pragma unroll
        for (int k = 0; k < 8; k++) {
            const float v = __shfl_up_sync(FULL, t[k], off, 16);
            if (l >= off) t[k] *= v;
        }
    }

    // exclusive scans + slab totals
    float excl[8], P[8];
    #pragma unroll
    for (int k = 0; k < 8; k++) {
        const float e = __shfl_up_sync(FULL, t[k], 1, 16);
        excl[k] = (l == 0) ? 1.0f : e;
        P[k]    = __shfl_sync(FULL, t[k], 15, 16);
    }

    // ---- weights & accumulation; colors reloaded from L1 ----
    float c0 = 0.f, c1 = 0.f, c2 = 0.f, wz = 0.f, ws = 0.f, S1 = 0.f;
    float Ck = 1.0f;
    #pragma unroll
    for (int k = 0; k < 8; k++) {
        const float4 rc = rp[16 * k + l];            // L1 hit (line already fetched)
        const float w = a[k] * (Ck * excl[k]);
        c0 += w * rc.x;
        c1 += w * rc.y;
        c2 += w * rc.z;
        wz += w * z[k];
        ws += w;
        S1 += w * __logf(fmaxf(w, 1e-35f));          // w*ln(w) -> 0 as w -> 0
        Ck *= P[k];
    }

    // ---- packed width-16 reduction: 15 SHFL total for all 6 values ----
    c0 += __shfl_xor_sync(FULL, c0, 8, 16);
    c1 += __shfl_xor_sync(FULL, c1, 8, 16);
    c2 += __shfl_xor_sync(FULL, c2, 8, 16);
    wz += __shfl_xor_sync(FULL, wz, 8, 16);
    ws += __shfl_xor_sync(FULL, ws, 8, 16);
    S1 += __shfl_xor_sync(FULL, S1, 8, 16);
    // lanes l<8 carry {c0,c1,c2}; lanes l>=8 carry {wz,ws,S1}
    float A = (l < 8) ? c0 : wz;
    float B = (l < 8) ? c1 : ws;
    float C = (l < 8) ? c2 : S1;
    #pragma unroll
    for (int off = 4; off > 0; off >>= 1) {
        A += __shfl_xor_sync(FULL, A, off, 16);
        B += __shfl_xor_sync(FULL, B, off, 16);
        C += __shfl_xor_sync(FULL, C, off, 16);
    }
    // lane 0 (and 16): Σc0 Σc1 Σc2 ; lane 8 (and 24): Σwz Σws ΣS1

    float ent = 0.0f;
    if (active && l == 0) {
        out[(size_t)ray * 3 + 0] = A;
        out[(size_t)ray * 3 + 1] = B;
        out[(size_t)ray * 3 + 2] = C;
    }
    if (active && l == 8) {
        const float wzs = A, wss = B, s1s = C;
        // depth = (1.5*ws - 0.25*wz)/(ws+1e-5)     [zn = (6-z)/4]
        out[(size_t)3 * N + ray] = (1.5f * wss - 0.25f * wzs) / (wss + 1e-5f);
        // sum p*ln p (p = w/(1+1e-6)) = invD*(S1 + ln(invD)*ws) + tail
        const float invD = 1.0f / (1.0f + 1e-6f);
        ent = invD * (s1s + (-9.999995e-7f) * wss);
        const float p_last = (1.0f - wss + 1e-6f) * invD;
        if (p_last > 0.0f) ent += p_last * __logf(p_last);
    }
    // combine ray A (lane 8) + ray B (lane 24) entropies
    ent += __shfl_xor_sync(FULL, ent, 16);
    if (lane == 8) sh_ent[warp] = ent;
    __syncthreads();

    // ---- fused deterministic grid reduction (threadfence-reduction pattern) ----
    if (threadIdx.x == 0) {
        float s = 0.0f;
        #pragma unroll
        for (int w = 0; w < TPB / 32; w++) s += sh_ent[w];
        g_partials[blockIdx.x] = s;
        __threadfence();
        const unsigned int done = atomicAdd(&g_count, 1u);
        sh_last = (done == gridDim.x - 1);
    }
    __syncthreads();

    if (sh_last) {
        double s = 0.0;
        for (int i = threadIdx.x; i < (int)gridDim.x; i += TPB)
            s += (double)g_partials[i];
        sh_red[threadIdx.x] = s;
        __syncthreads();
        #pragma unroll
        for (int off = TPB / 2; off > 0; off >>= 1) {
            if (threadIdx.x < off) sh_red[threadIdx.x] += sh_red[threadIdx.x + off];
            __syncthreads();
        }
        if (threadIdx.x == 0) {
            out[(size_t)4 * N] = (float)(-sh_red[0]);   // sparsity_loss
            g_count = 0;                                 // re-arm for next replay
        }
    }
}

extern "C" void kernel_launch(void* const* d_in, const int* in_sizes, int n_in,
                              void* d_out, int out_size)
{
    const float* raw    = (const float*)d_in[0];
    const float* zvals  = (const float*)d_in[1];
    const float* rays_d = (const float*)d_in[2];
    float* out = (float*)d_out;

    const int N = in_sizes[2] / 3;               // rays_d is [N,3]
    const int raysPerBlock = (TPB / 32) * 2;     // 8
    const int blocks = (N + raysPerBlock - 1) / raysPerBlock;

    integrate_kernel<<<blocks, TPB>>>(raw, zvals, rays_d, out, N);
}

// round 14
// speedup vs baseline: 1.2342x; 1.2342x over previous
#include <cuda_runtime.h>
#include <math.h>

#define NEARV     2.0f
#define FARV      6.0f
#define FAR_DIST  1e10f
#define S         128
#define TPB       128          // 4 warps, 8 rays per block
#define MAX_BLK   16384
#define FULL      0xffffffffu
#define ONE_EPS   1.0000000001f   // 1 + 1e-10

// Deterministic scratch for the fused scalar reduction (no allocations allowed).
__device__ float        g_partials[MAX_BLK];
__device__ unsigned int g_count = 0;

__global__ __launch_bounds__(TPB, 8) void integrate_kernel(
    const float* __restrict__ raw,     // [N, S, 4]
    const float* __restrict__ zvals,   // [N, S]
    const float* __restrict__ rays_d,  // [N, 3]
    float* __restrict__ out,           // [3N chs | N depth | 1 scalar]
    int N)
{
    __shared__ float  sh_ent[TPB / 32];
    __shared__ double sh_red[TPB];
    __shared__ bool   sh_last;

    const int warp = threadIdx.x >> 5;
    const int lane = threadIdx.x & 31;
    const int half = lane >> 4;              // 0 -> ray A, 1 -> ray B
    const int l    = lane & 15;              // lane within 16-lane ray group
    int ray = (blockIdx.x * (TPB >> 5) + warp) * 2 + half;
    const bool active = (ray < N);
    if (!active) ray = N - 1;                // clamp: safe reads, stores guarded

    // ---- front-batched fully-coalesced loads: lane owns j = 16k + l ----
    const float4* rp = (const float4*)raw + (size_t)ray * S;
    const float*  zp = zvals + (size_t)ray * S;

    float4 r[8];
    #pragma unroll
    for (int k = 0; k < 8; k++) r[k] = rp[16 * k + l];

    float z[8];
    #pragma unroll
    for (int k = 0; k < 8; k++) z[k] = zp[16 * k + l];

    const float* rd = rays_d + (size_t)ray * 3;
    const float nrm = sqrtf(rd[0] * rd[0] + rd[1] * rd[1] + rd[2] * rd[2]);

    // ---- transmittance factors t = e + 1e-10 (alpha derived later) ----
    // z-next comes from shuffles: within-segment shfl_down + slab-head bcast.
    float t[8];
    #pragma unroll
    for (int k = 0; k < 8; k++) {
        const float znext = __shfl_down_sync(FULL, z[k], 1, 16);
        float dist;
        if (k < 7) {
            const float zhead = __shfl_sync(FULL, z[k + 1], 0, 16);
            dist = (l == 15) ? (zhead - z[k]) : (znext - z[k]);
        } else {
            dist = (l == 15) ? FAR_DIST : (znext - z[k]);
        }
        dist *= nrm;
        t[k] = __expf(-fmaxf(r[k].w, 0.0f) * dist) + 1e-10f;
    }

    // ---- 8 segmented (width-16) inclusive multiplicative scans (in place) ----
    #pragma unroll
    for (int off = 1; off < 16; off <<= 1) {
        #pragma unroll
        for (int k = 0; k < 8; k++) {
            const float v = __shfl_up_sync(FULL, t[k], off, 16);
            if (l >= off) t[k] *= v;
        }
    }
    // t[k] is now incl[k]

    // ---- weights & accumulation: w = Ck*(ONE_EPS*excl - incl) ----
    float c0 = 0.f, c1 = 0.f, c2 = 0.f, wz = 0.f, ws = 0.f, S1 = 0.f;
    float Ck = 1.0f;
    #pragma unroll
    for (int k = 0; k < 8; k++) {
        const float e  = __shfl_up_sync(FULL, t[k], 1, 16);
        const float ex = (l == 0) ? 1.0f : e;
        const float P  = __shfl_sync(FULL, t[k], 15, 16);
        const float w  = Ck * (ONE_EPS * ex - t[k]);
        c0 += w * r[k].x;
        c1 += w * r[k].y;
        c2 += w * r[k].z;
        wz += w * z[k];
        ws += w;
        S1 += w * __logf(fmaxf(w, 1e-35f));          // w*ln(w) -> 0 as w -> 0
        Ck *= P;
    }

    // ---- packed width-16 reduction: 15 SHFL total for all 6 values ----
    c0 += __shfl_xor_sync(FULL, c0, 8, 16);
    c1 += __shfl_xor_sync(FULL, c1, 8, 16);
    c2 += __shfl_xor_sync(FULL, c2, 8, 16);
    wz += __shfl_xor_sync(FULL, wz, 8, 16);
    ws += __shfl_xor_sync(FULL, ws, 8, 16);
    S1 += __shfl_xor_sync(FULL, S1, 8, 16);
    // lanes l<8 carry {c0,c1,c2}; lanes l>=8 carry {wz,ws,S1}
    float A = (l < 8) ? c0 : wz;
    float B = (l < 8) ? c1 : ws;
    float C = (l < 8) ? c2 : S1;
    #pragma unroll
    for (int off = 4; off > 0; off >>= 1) {
        A += __shfl_xor_sync(FULL, A, off, 16);
        B += __shfl_xor_sync(FULL, B, off, 16);
        C += __shfl_xor_sync(FULL, C, off, 16);
    }
    // lane 0 (and 16): Σc0 Σc1 Σc2 ; lane 8 (and 24): Σwz Σws ΣS1

    float ent = 0.0f;
    if (active && l == 0) {
        out[(size_t)ray * 3 + 0] = A;
        out[(size_t)ray * 3 + 1] = B;
        out[(size_t)ray * 3 + 2] = C;
    }
    if (active && l == 8) {
        const float wzs = A, wss = B, s1s = C;
        // depth = (1.5*ws - 0.25*wz)/(ws+1e-5)     [zn = (6-z)/4]
        out[(size_t)3 * N + ray] = (1.5f * wss - 0.25f * wzs) / (wss + 1e-5f);
        // sum p*ln p (p = w/(1+1e-6)) = invD*(S1 + ln(invD)*ws) + tail
        const float invD = 1.0f / (1.0f + 1e-6f);
        ent = invD * (s1s + (-9.999995e-7f) * wss);
        const float p_last = (1.0f - wss + 1e-6f) * invD;
        if (p_last > 0.0f) ent += p_last * __logf(p_last);
    }
    // combine ray A (lane 8) + ray B (lane 24) entropies
    ent += __shfl_xor_sync(FULL, ent, 16);
    if (lane == 8) sh_ent[warp] = ent;
    __syncthreads();

    // ---- fused deterministic grid reduction (threadfence-reduction pattern) ----
    if (threadIdx.x == 0) {
        float s = 0.0f;
        #pragma unroll
        for (int w = 0; w < TPB / 32; w++) s += sh_ent[w];
        g_partials[blockIdx.x] = s;
        __threadfence();
        const unsigned int done = atomicAdd(&g_count, 1u);
        sh_last = (done == gridDim.x - 1);
    }
    __syncthreads();

    if (sh_last) {
        double s = 0.0;
        for (int i = threadIdx.x; i < (int)gridDim.x; i += TPB)
            s += (double)g_partials[i];
        sh_red[threadIdx.x] = s;
        __syncthreads();
        #pragma unroll
        for (int off = TPB / 2; off > 0; off >>= 1) {
            if (threadIdx.x < off) sh_red[threadIdx.x] += sh_red[threadIdx.x + off];
            __syncthreads();
        }
        if (threadIdx.x == 0) {
            out[(size_t)4 * N] = (float)(-sh_red[0]);   // sparsity_loss
            g_count = 0;                                 // re-arm for next replay
        }
    }
}

extern "C" void kernel_launch(void* const* d_in, const int* in_sizes, int n_in,
                              void* d_out, int out_size)
{
    const float* raw    = (const float*)d_in[0];
    const float* zvals  = (const float*)d_in[1];
    const float* rays_d = (const float*)d_in[2];
    float* out = (float*)d_out;

    const int N = in_sizes[2] / 3;               // rays_d is [N,3]
    const int raysPerBlock = (TPB / 32) * 2;     // 8
    const int blocks = (N + raysPerBlock - 1) / raysPerBlock;

    integrate_kernel<<<blocks, TPB>>>(raw, zvals, rays_d, out, N);
}